// round 5
// baseline (speedup 1.0000x reference)
#include <cuda_runtime.h>
#include <cstdint>

// Edge-wise u·v scoring (DGL fn.u_dot_v)
//   d_in[0] user_h : [100000, 128] float32
//   d_in[1] game_h : [ 50000, 128] float32
//   d_in[2] src_idx: [E] int32
//   d_in[3] dst_idx: [E] int32
//   d_out   score  : [E, 1] float32
//
// R5: mixed LDG.64 / LDG.32 pattern to balance the L1tex wavefront-replay
// cost (~2.07 cyc/wf for multi-wf LDGs) against the LSU issue floor
// (~1.82 cyc/LDG SM-wide). Per edge: lower 64 floats of both rows via one
// LDG.64 each, upper 64 via two LDG.32 each -> 12.3 wf-cyc vs 10.9 issue-cyc.
// Indices: two uniform int4 loads per warp instead of 8 scalar loads.

#define WARPS_PER_BLOCK 8
#define THREADS_PER_BLOCK (WARPS_PER_BLOCK * 32)
#define EDGES_PER_WARP 4

__global__ void __launch_bounds__(THREADS_PER_BLOCK)
edge_dot_kernel(const float* __restrict__ user_h,
                const float* __restrict__ game_h,
                const int* __restrict__ src_idx,
                const int* __restrict__ dst_idx,
                float* __restrict__ out,
                int num_edges,
                int n_users,
                int n_games)
{
    const int warp_in_block = threadIdx.x >> 5;
    const int lane          = threadIdx.x & 31;
    const int warp_id = blockIdx.x * WARPS_PER_BLOCK + warp_in_block;
    const int e0 = warp_id * EDGES_PER_WARP;
    if (e0 >= num_edges) return;

    if (e0 + EDGES_PER_WARP <= num_edges) {
        // ---- fast path: 4 edges ----
        // Uniform (warp-broadcast) vector index loads; e0 is a multiple of 4
        // -> 16B aligned.
        const int4 sv = *reinterpret_cast<const int4*>(src_idx + e0);
        const int4 dv = *reinterpret_cast<const int4*>(dst_idx + e0);
        int su[EDGES_PER_WARP] = { sv.x, sv.y, sv.z, sv.w };
        int sg[EDGES_PER_WARP] = { dv.x, dv.y, dv.z, dv.w };
        #pragma unroll
        for (int i = 0; i < EDGES_PER_WARP; i++) {
            su[i] = min(max(su[i], 0), n_users - 1);
            sg[i] = min(max(sg[i], 0), n_games - 1);
        }

        // Per edge: lower half (floats 0..63) via LDG.64 (lane -> {2l,2l+1}),
        // upper half via two LDG.32 (lane -> {64+l}, {96+l}).
        // Per-lane element pairing between u and v is identical in each part.
        float2 ulo[EDGES_PER_WARP], vlo[EDGES_PER_WARP];
        float  ua[EDGES_PER_WARP], ub[EDGES_PER_WARP];
        float  va[EDGES_PER_WARP], vb[EDGES_PER_WARP];
        #pragma unroll
        for (int i = 0; i < EDGES_PER_WARP; i++) {
            const float* up = user_h + (size_t)su[i] * 128;
            const float* gp = game_h + (size_t)sg[i] * 128;
            ulo[i] = __ldcg(reinterpret_cast<const float2*>(up) + lane);
            vlo[i] = __ldcg(reinterpret_cast<const float2*>(gp) + lane);
            ua[i]  = __ldcg(up + 64 + lane);
            ub[i]  = __ldcg(up + 96 + lane);
            va[i]  = __ldcg(gp + 64 + lane);
            vb[i]  = __ldcg(gp + 96 + lane);
        }

        float acc[EDGES_PER_WARP];
        #pragma unroll
        for (int i = 0; i < EDGES_PER_WARP; i++) {
            float a = ulo[i].x * vlo[i].x;
            a = fmaf(ulo[i].y, vlo[i].y, a);
            a = fmaf(ua[i], va[i], a);
            a = fmaf(ub[i], vb[i], a);
            acc[i] = a;
        }

        // Split butterfly: 3 shared-width stages per edge, then lane-group
        // select and 2 final stages (14 shuffles total for 4 edges).
        #pragma unroll
        for (int i = 0; i < EDGES_PER_WARP; i++) {
            acc[i] += __shfl_xor_sync(0xFFFFFFFFu, acc[i], 16);
            acc[i] += __shfl_xor_sync(0xFFFFFFFFu, acc[i], 8);
            acc[i] += __shfl_xor_sync(0xFFFFFFFFu, acc[i], 4);
        }
        const int j = (lane >> 2) & 3;
        float val = acc[0];
        if (j == 1) val = acc[1];
        if (j == 2) val = acc[2];
        if (j == 3) val = acc[3];
        val += __shfl_xor_sync(0xFFFFFFFFu, val, 2);
        val += __shfl_xor_sync(0xFFFFFFFFu, val, 1);

        if ((lane & 3) == 0 && lane < 16)
            out[e0 + j] = val;
    } else {
        // ---- tail: per-edge ----
        for (int e = e0; e < num_edges; e++) {
            int su = min(max(src_idx[e], 0), n_users - 1);
            int sg = min(max(dst_idx[e], 0), n_games - 1);
            const float* up = user_h + (size_t)su * 128;
            const float* gp = game_h + (size_t)sg * 128;
            float2 u0 = __ldcg(reinterpret_cast<const float2*>(up) + lane);
            float2 v0 = __ldcg(reinterpret_cast<const float2*>(gp) + lane);
            float  u1 = __ldcg(up + 64 + lane);
            float  u2 = __ldcg(up + 96 + lane);
            float  v1 = __ldcg(gp + 64 + lane);
            float  v2 = __ldcg(gp + 96 + lane);
            float a = u0.x * v0.x;
            a = fmaf(u0.y, v0.y, a);
            a = fmaf(u1, v1, a);
            a = fmaf(u2, v2, a);
            #pragma unroll
            for (int ofs = 16; ofs > 0; ofs >>= 1)
                a += __shfl_xor_sync(0xFFFFFFFFu, a, ofs);
            if (lane == 0) out[e] = a;
        }
    }
}

extern "C" void kernel_launch(void* const* d_in, const int* in_sizes, int n_in,
                              void* d_out, int out_size)
{
    const float* user_h  = (const float*)d_in[0];
    const float* game_h  = (const float*)d_in[1];
    const int*   src_idx = (const int*)d_in[2];
    const int*   dst_idx = (const int*)d_in[3];
    float*       out     = (float*)d_out;

    const int num_edges = in_sizes[2];
    const int n_users   = in_sizes[0] / 128;
    const int n_games   = in_sizes[1] / 128;

    const int edges_per_block = WARPS_PER_BLOCK * EDGES_PER_WARP;
    const int grid = (num_edges + edges_per_block - 1) / edges_per_block;
    edge_dot_kernel<<<grid, THREADS_PER_BLOCK>>>(
        user_h, game_h, src_idx, dst_idx, out, num_edges, n_users, n_games);
}

// round 7
// speedup vs baseline: 1.2405x; 1.2405x over previous
#include <cuda_runtime.h>
#include <cstdint>

// Edge-wise u·v scoring (DGL fn.u_dot_v)
//   d_in[0] user_h : [100000, 128] float32
//   d_in[1] game_h : [ 50000, 128] float32
//   d_in[2] src_idx: [E] int32
//   d_in[3] dst_idx: [E] int32
//   d_out   score  : [E, 1] float32
//
// R6 (resubmit after infra failure): persistent grid-stride kernel.
// Cross-round evidence shows L1tex cost is per-128B-wavefront (~1.9 cyc/wf,
// 8 wf/edge) regardless of LDG width, so the load pattern is R4's best
// (4x LDG.64 per edge, .cg). Win target: L1 busy 84.7% -> ~95% by killing
// one-shot-CTA churn and overlapping two edge-groups per warp (unroll 2).

#define WARPS_PER_BLOCK 8
#define THREADS_PER_BLOCK (WARPS_PER_BLOCK * 32)
#define EDGES_PER_WARP 4
#define GRID_BLOCKS 2368   // 148 SMs * 16 persistent blocks

__global__ void __launch_bounds__(THREADS_PER_BLOCK)
edge_dot_kernel(const float* __restrict__ user_h,
                const float* __restrict__ game_h,
                const int* __restrict__ src_idx,
                const int* __restrict__ dst_idx,
                float* __restrict__ out,
                int num_edges,
                int n_users,
                int n_games)
{
    const int lane  = threadIdx.x & 31;
    const int gwarp = blockIdx.x * WARPS_PER_BLOCK + (threadIdx.x >> 5);
    const int nwarp = GRID_BLOCKS * WARPS_PER_BLOCK;

    const int ngroups = num_edges >> 2;   // full groups of 4 edges

    #pragma unroll 2
    for (int g = gwarp; g < ngroups; g += nwarp) {
        const int e0 = g << 2;

        // Uniform (warp-broadcast) vector index loads; e0 % 4 == 0 -> 16B aligned.
        const int4 sv = *reinterpret_cast<const int4*>(src_idx + e0);
        const int4 dv = *reinterpret_cast<const int4*>(dst_idx + e0);
        int su[EDGES_PER_WARP] = { sv.x, sv.y, sv.z, sv.w };
        int sg[EDGES_PER_WARP] = { dv.x, dv.y, dv.z, dv.w };
        #pragma unroll
        for (int i = 0; i < EDGES_PER_WARP; i++) {
            su[i] = min(max(su[i], 0), n_users - 1);
            sg[i] = min(max(sg[i], 0), n_games - 1);
        }

        // 16 independent LDG.64s (row = 64 float2; lane covers {lane, lane+32}).
        float2 u0[EDGES_PER_WARP], u1[EDGES_PER_WARP];
        float2 v0[EDGES_PER_WARP], v1[EDGES_PER_WARP];
        #pragma unroll
        for (int i = 0; i < EDGES_PER_WARP; i++) {
            const float2* up = reinterpret_cast<const float2*>(
                                   user_h + (size_t)su[i] * 128);
            const float2* gp = reinterpret_cast<const float2*>(
                                   game_h + (size_t)sg[i] * 128);
            u0[i] = __ldcg(up + lane);
            u1[i] = __ldcg(up + lane + 32);
            v0[i] = __ldcg(gp + lane);
            v1[i] = __ldcg(gp + lane + 32);
        }

        float acc[EDGES_PER_WARP];
        #pragma unroll
        for (int i = 0; i < EDGES_PER_WARP; i++) {
            float a = u0[i].x * v0[i].x;
            a = fmaf(u0[i].y, v0[i].y, a);
            a = fmaf(u1[i].x, v1[i].x, a);
            a = fmaf(u1[i].y, v1[i].y, a);
            acc[i] = a;
        }

        // Split butterfly: 3 shared-width stages per edge, then lane-group
        // select and 2 final stages (14 shuffles total for 4 edges).
        #pragma unroll
        for (int i = 0; i < EDGES_PER_WARP; i++) {
            acc[i] += __shfl_xor_sync(0xFFFFFFFFu, acc[i], 16);
            acc[i] += __shfl_xor_sync(0xFFFFFFFFu, acc[i], 8);
            acc[i] += __shfl_xor_sync(0xFFFFFFFFu, acc[i], 4);
        }
        const int j = (lane >> 2) & 3;
        float val = acc[0];
        if (j == 1) val = acc[1];
        if (j == 2) val = acc[2];
        if (j == 3) val = acc[3];
        val += __shfl_xor_sync(0xFFFFFFFFu, val, 2);
        val += __shfl_xor_sync(0xFFFFFFFFu, val, 1);

        // lanes 0,4,8,12 write edges e0+0..3 (single wavefront).
        if ((lane & 3) == 0 && lane < 16)
            out[e0 + j] = val;
    }

    // Tail edges (num_edges % 4), handled by warp 0 of block 0, full-warp dot.
    if (blockIdx.x == 0 && (threadIdx.x >> 5) == 0) {
        for (int e = ngroups << 2; e < num_edges; e++) {
            int su = min(max(src_idx[e], 0), n_users - 1);
            int sg = min(max(dst_idx[e], 0), n_games - 1);
            const float2* up = reinterpret_cast<const float2*>(
                                   user_h + (size_t)su * 128);
            const float2* gp = reinterpret_cast<const float2*>(
                                   game_h + (size_t)sg * 128);
            float2 a0 = __ldcg(up + lane);
            float2 a1 = __ldcg(up + lane + 32);
            float2 b0 = __ldcg(gp + lane);
            float2 b1 = __ldcg(gp + lane + 32);
            float a = a0.x * b0.x;
            a = fmaf(a0.y, b0.y, a);
            a = fmaf(a1.x, b1.x, a);
            a = fmaf(a1.y, b1.y, a);
            #pragma unroll
            for (int ofs = 16; ofs > 0; ofs >>= 1)
                a += __shfl_xor_sync(0xFFFFFFFFu, a, ofs);
            if (lane == 0) out[e] = a;
        }
    }
}

extern "C" void kernel_launch(void* const* d_in, const int* in_sizes, int n_in,
                              void* d_out, int out_size)
{
    const float* user_h  = (const float*)d_in[0];
    const float* game_h  = (const float*)d_in[1];
    const int*   src_idx = (const int*)d_in[2];
    const int*   dst_idx = (const int*)d_in[3];
    float*       out     = (float*)d_out;

    const int num_edges = in_sizes[2];
    const int n_users   = in_sizes[0] / 128;
    const int n_games   = in_sizes[1] / 128;

    edge_dot_kernel<<<GRID_BLOCKS, THREADS_PER_BLOCK>>>(
        user_h, game_h, src_idx, dst_idx, out, num_edges, n_users, n_games);
}